// round 16
// baseline (speedup 1.0000x reference)
#include <cuda_runtime.h>
#include <cuda_fp16.h>
#include <mma.h>
#include <math.h>
#include <stdint.h>

using namespace nvcuda;

#define T_TOK 2048
#define DHID  1024
#define FINT  1408
#define NEXP  8

// ---------------- device scratch (static: no allocations allowed) ----------
__device__ int            g_count[NEXP];
__device__ int            g_tok[NEXP * T_TOK];
__device__ float          g_wt [NEXP * T_TOK];
__device__ unsigned char  g_kslot[NEXP * T_TOK];

__device__ __half         g_x16[(size_t)NEXP * T_TOK * DHID];
__device__ __half         g_wg16[(size_t)NEXP * DHID * FINT];
__device__ __half         g_wu16[(size_t)NEXP * DHID * FINT];
__device__ __half         g_wd16[(size_t)NEXP * FINT * DHID];
__device__ __half         g_h16[(size_t)NEXP * T_TOK * FINT];
__device__ float          g_y[(size_t)T_TOK * 2 * DHID];

// ---------------- routing ---------------------------------------------------
__global__ void zero_counts_kernel() {
    if (threadIdx.x < NEXP) g_count[threadIdx.x] = 0;
}

__global__ void router_kernel(const float* __restrict__ x,
                              const float* __restrict__ rw) {
    int warp = (blockIdx.x * blockDim.x + threadIdx.x) >> 5;
    int lane = threadIdx.x & 31;
    if (warp >= T_TOK) return;
    const float* xt = x + (size_t)warp * DHID;

    float logit[NEXP];
#pragma unroll
    for (int e = 0; e < NEXP; e++) {
        const float* w = rw + (size_t)e * DHID;
        float s = 0.f;
        for (int i = lane; i < DHID; i += 32) s += xt[i] * w[i];
#pragma unroll
        for (int o = 16; o > 0; o >>= 1) s += __shfl_xor_sync(0xffffffffu, s, o);
        logit[e] = s;
    }
    if (lane == 0) {
        float m = logit[0];
#pragma unroll
        for (int e = 1; e < NEXP; e++) m = fmaxf(m, logit[e]);
        float p[NEXP];
#pragma unroll
        for (int e = 0; e < NEXP; e++) p[e] = expf(logit[e] - m);
        int i1 = 0; float v1 = p[0];
#pragma unroll
        for (int e = 1; e < NEXP; e++) if (p[e] > v1) { v1 = p[e]; i1 = e; }
        int i2 = -1; float v2 = -1.f;
#pragma unroll
        for (int e = 0; e < NEXP; e++) {
            if (e == i1) continue;
            if (p[e] > v2) { v2 = p[e]; i2 = e; }
        }
        float inv = 1.f / (v1 + v2);
        int pos1 = atomicAdd(&g_count[i1], 1);
        g_tok[i1 * T_TOK + pos1] = warp;  g_wt[i1 * T_TOK + pos1] = v1 * inv;  g_kslot[i1 * T_TOK + pos1] = 0;
        int pos2 = atomicAdd(&g_count[i2], 1);
        g_tok[i2 * T_TOK + pos2] = warp;  g_wt[i2 * T_TOK + pos2] = v2 * inv;  g_kslot[i2 * T_TOK + pos2] = 1;
    }
}

// gather routed tokens into per-expert contiguous fp16 rows (vectorized)
__global__ void gather_x_kernel(const float* __restrict__ x) {
    int s = blockIdx.x, e = blockIdx.y;
    if (s >= g_count[e]) return;
    int t = g_tok[e * T_TOK + s];
    const float* src = x + (size_t)t * DHID;
    __half* dst = g_x16 + ((size_t)e * T_TOK + s) * DHID;
    int i = threadIdx.x * 8;
    float4 v0 = *(const float4*)(src + i);
    float4 v1 = *(const float4*)(src + i + 4);
    __half h[8];
    h[0] = __float2half_rn(v0.x); h[1] = __float2half_rn(v0.y);
    h[2] = __float2half_rn(v0.z); h[3] = __float2half_rn(v0.w);
    h[4] = __float2half_rn(v1.x); h[5] = __float2half_rn(v1.y);
    h[6] = __float2half_rn(v1.z); h[7] = __float2half_rn(v1.w);
    *(uint4*)(dst + i) = *(uint4*)h;
}

// pre-convert fp32 weights -> fp16 (dest chosen in device code)
__global__ void __launch_bounds__(256) conv_kernel(const float* __restrict__ wg,
                                                   const float* __restrict__ wu,
                                                   const float* __restrict__ wd) {
    int which = blockIdx.y;
    const float* src = (which == 0) ? wg : (which == 1) ? wu : wd;
    __half* dst = (which == 0) ? g_wg16 : (which == 1) ? g_wu16 : g_wd16;
    size_t i = ((size_t)blockIdx.x * 256 + threadIdx.x) * 8;
    float4 v0 = *(const float4*)(src + i);
    float4 v1 = *(const float4*)(src + i + 4);
    __half h[8];
    h[0] = __float2half_rn(v0.x); h[1] = __float2half_rn(v0.y);
    h[2] = __float2half_rn(v0.z); h[3] = __float2half_rn(v0.w);
    h[4] = __float2half_rn(v1.x); h[5] = __float2half_rn(v1.y);
    h[6] = __float2half_rn(v1.z); h[7] = __float2half_rn(v1.w);
    *(uint4*)(dst + i) = *(uint4*)h;
}

// ---------------- gate+up WMMA GEMM: 64m x 64n, 4 warps, 4 CTAs/SM ---------
// Warp grid 2m x 2n, warp tile 32x32 per matrix (gate+up).
__global__ void __launch_bounds__(128, 4) gu_wmma_kernel() {
    int e   = blockIdx.z;
    int cnt = g_count[e];
    int m0  = blockIdx.y * 64;
    if (m0 >= cnt) return;
    int n0  = blockIdx.x * 64;

    __shared__ union {
        struct {
            __half A[2][64][40];      // 10240 B
            __half B[2][2][32][72];   // 18432 B
        } ld;
        float ebuf[4][32 * 36];       // 18432 B
    } sm;

    int tid = threadIdx.x, wid = tid >> 5, lane = tid & 31;
    int wm = wid & 1, wn = wid >> 1;

    const __half* W0 = g_wg16 + (size_t)e * DHID * FINT + n0;
    const __half* W1 = g_wu16 + (size_t)e * DHID * FINT + n0;
    size_t aBase = (size_t)e * T_TOK + m0;

    int ar = tid >> 2, ac = tid & 3;      // A rows ar, ar+32; col chunk ac
    int bk = tid >> 3, bc = tid & 7;      // B rows bk, bk+16 (each mat)

    const __half* aP0 = g_x16 + (aBase + ar)      * DHID + ac * 8;
    const __half* aP1 = g_x16 + (aBase + ar + 32) * DHID + ac * 8;
    const __half* gP0 = W0 + (size_t)bk * FINT + bc * 8;
    const __half* gP1 = W0 + (size_t)(bk + 16) * FINT + bc * 8;
    const __half* uP0 = W1 + (size_t)bk * FINT + bc * 8;
    const __half* uP1 = W1 + (size_t)(bk + 16) * FINT + bc * 8;

    wmma::fragment<wmma::accumulator, 16, 16, 16, float> c[2][2][2];
#pragma unroll
    for (int mat = 0; mat < 2; mat++)
#pragma unroll
        for (int mf = 0; mf < 2; mf++)
#pragma unroll
            for (int nf = 0; nf < 2; nf++)
                wmma::fill_fragment(c[mat][mf][nf], 0.0f);

    uint4 ra0, ra1, rg0, rg1, ru0, ru1;
    ra0 = *(const uint4*)(aP0);
    ra1 = *(const uint4*)(aP1);
    rg0 = *(const uint4*)(gP0);
    rg1 = *(const uint4*)(gP1);
    ru0 = *(const uint4*)(uP0);
    ru1 = *(const uint4*)(uP1);

    const int NT = DHID / 32;   // 32
    for (int t = 0; t < NT; t++) {
        int b = t & 1;
        *(uint4*)&sm.ld.A[b][ar][ac * 8]         = ra0;
        *(uint4*)&sm.ld.A[b][ar + 32][ac * 8]    = ra1;
        *(uint4*)&sm.ld.B[b][0][bk][bc * 8]      = rg0;
        *(uint4*)&sm.ld.B[b][0][bk + 16][bc * 8] = rg1;
        *(uint4*)&sm.ld.B[b][1][bk][bc * 8]      = ru0;
        *(uint4*)&sm.ld.B[b][1][bk + 16][bc * 8] = ru1;
        __syncthreads();
        if (t + 1 < NT) {
            int k1 = (t + 1) * 32;
            ra0 = *(const uint4*)(aP0 + k1);
            ra1 = *(const uint4*)(aP1 + k1);
            rg0 = *(const uint4*)(gP0 + (size_t)k1 * FINT);
            rg1 = *(const uint4*)(gP1 + (size_t)k1 * FINT);
            ru0 = *(const uint4*)(uP0 + (size_t)k1 * FINT);
            ru1 = *(const uint4*)(uP1 + (size_t)k1 * FINT);
        }

#pragma unroll
        for (int kk16 = 0; kk16 < 32; kk16 += 16) {
            wmma::fragment<wmma::matrix_a, 16, 16, 16, __half, wmma::row_major> a[2];
#pragma unroll
            for (int mf = 0; mf < 2; mf++)
                wmma::load_matrix_sync(a[mf], &sm.ld.A[b][wm * 32 + mf * 16][kk16], 40);
#pragma unroll
            for (int mat = 0; mat < 2; mat++) {
#pragma unroll
                for (int nf = 0; nf < 2; nf++) {
                    wmma::fragment<wmma::matrix_b, 16, 16, 16, __half, wmma::row_major> bfr;
                    wmma::load_matrix_sync(bfr, &sm.ld.B[b][mat][kk16][wn * 32 + nf * 16], 72);
#pragma unroll
                    for (int mf = 0; mf < 2; mf++)
                        wmma::mma_sync(c[mat][mf][nf], a[mf], bfr, c[mat][mf][nf]);
                }
            }
        }
    }

    // ---- fused SwiGLU epilogue ----
    __syncthreads();
    float* buf = sm.ebuf[wid];
    int grow = m0 + wm * 32 + lane;
    bool ok = grow < cnt;
    size_t hbase = ((size_t)e * T_TOK + grow) * FINT + n0 + wn * 32;

#pragma unroll
    for (int mf = 0; mf < 2; mf++)
#pragma unroll
        for (int nf = 0; nf < 2; nf++)
            wmma::store_matrix_sync(&buf[mf * 16 * 36 + nf * 16], c[0][mf][nf], 36, wmma::mem_row_major);
    __syncwarp();
    float gv[32];
#pragma unroll
    for (int j = 0; j < 32; j++) gv[j] = buf[lane * 36 + j];
    __syncwarp();
#pragma unroll
    for (int mf = 0; mf < 2; mf++)
#pragma unroll
        for (int nf = 0; nf < 2; nf++)
            wmma::store_matrix_sync(&buf[mf * 16 * 36 + nf * 16], c[1][mf][nf], 36, wmma::mem_row_major);
    __syncwarp();
    if (ok) {
#pragma unroll
        for (int j = 0; j < 32; j += 2) {
            float u0 = buf[lane * 36 + j];
            float u1 = buf[lane * 36 + j + 1];
            float g0 = gv[j], g1 = gv[j + 1];
            float h0 = g0 / (1.f + expf(-g0)) * u0;
            float h1 = g1 / (1.f + expf(-g1)) * u1;
            __half2 vh;
            vh.x = __float2half_rn(h0);
            vh.y = __float2half_rn(h1);
            *(__half2*)&g_h16[hbase + j] = vh;
        }
    }
}

// ---------------- down WMMA GEMM: 64m x 128n, 4 warps, 4 CTAs/SM -----------
// Warp grid 2m x 2n, warp tile 32 x 64.
__global__ void __launch_bounds__(128, 4) down_wmma_kernel() {
    int e   = blockIdx.z;
    int cnt = g_count[e];
    int m0  = blockIdx.y * 64;
    if (m0 >= cnt) return;
    int n0  = blockIdx.x * 128;

    __shared__ union {
        struct {
            __half A[2][64][40];      // 10240 B
            __half B[2][32][136];     // 17408 B
        } ld;
        float ebuf[4][32 * 36];
    } sm;

    int tid = threadIdx.x, wid = tid >> 5, lane = tid & 31;
    int wm = wid & 1, wn = wid >> 1;

    const __half* W = g_wd16 + (size_t)e * FINT * DHID + n0;
    size_t aBase = (size_t)e * T_TOK + m0;

    int ar = tid >> 2, ac = tid & 3;      // A rows ar, ar+32
    int bk = tid >> 4, bc = tid & 15;     // B rows bk, +8, +16, +24

    const __half* aP0 = g_h16 + (aBase + ar)      * FINT + ac * 8;
    const __half* aP1 = g_h16 + (aBase + ar + 32) * FINT + ac * 8;
    const __half* bP0 = W + (size_t)bk * DHID + bc * 8;
    const __half* bP1 = W + (size_t)(bk + 8)  * DHID + bc * 8;
    const __half* bP2 = W + (size_t)(bk + 16) * DHID + bc * 8;
    const __half* bP3 = W + (size_t)(bk + 24) * DHID + bc * 8;

    wmma::fragment<wmma::accumulator, 16, 16, 16, float> c[2][4];
#pragma unroll
    for (int mf = 0; mf < 2; mf++)
#pragma unroll
        for (int nf = 0; nf < 4; nf++)
            wmma::fill_fragment(c[mf][nf], 0.0f);

    uint4 ra0, ra1, rb0, rb1, rb2, rb3;
    ra0 = *(const uint4*)(aP0);
    ra1 = *(const uint4*)(aP1);
    rb0 = *(const uint4*)(bP0);
    rb1 = *(const uint4*)(bP1);
    rb2 = *(const uint4*)(bP2);
    rb3 = *(const uint4*)(bP3);

    const int NT = FINT / 32;   // 44
    for (int t = 0; t < NT; t++) {
        int b = t & 1;
        *(uint4*)&sm.ld.A[b][ar][ac * 8]        = ra0;
        *(uint4*)&sm.ld.A[b][ar + 32][ac * 8]   = ra1;
        *(uint4*)&sm.ld.B[b][bk][bc * 8]        = rb0;
        *(uint4*)&sm.ld.B[b][bk + 8][bc * 8]    = rb1;
        *(uint4*)&sm.ld.B[b][bk + 16][bc * 8]   = rb2;
        *(uint4*)&sm.ld.B[b][bk + 24][bc * 8]   = rb3;
        __syncthreads();
        if (t + 1 < NT) {
            int k1 = (t + 1) * 32;
            ra0 = *(const uint4*)(aP0 + k1);
            ra1 = *(const uint4*)(aP1 + k1);
            rb0 = *(const uint4*)(bP0 + (size_t)k1 * DHID);
            rb1 = *(const uint4*)(bP1 + (size_t)k1 * DHID);
            rb2 = *(const uint4*)(bP2 + (size_t)k1 * DHID);
            rb3 = *(const uint4*)(bP3 + (size_t)k1 * DHID);
        }

#pragma unroll
        for (int kk16 = 0; kk16 < 32; kk16 += 16) {
            wmma::fragment<wmma::matrix_a, 16, 16, 16, __half, wmma::row_major> a[2];
#pragma unroll
            for (int mf = 0; mf < 2; mf++)
                wmma::load_matrix_sync(a[mf], &sm.ld.A[b][wm * 32 + mf * 16][kk16], 40);
#pragma unroll
            for (int nf = 0; nf < 4; nf++) {
                wmma::fragment<wmma::matrix_b, 16, 16, 16, __half, wmma::row_major> bfr;
                wmma::load_matrix_sync(bfr, &sm.ld.B[b][kk16][wn * 64 + nf * 16], 136);
#pragma unroll
                for (int mf = 0; mf < 2; mf++)
                    wmma::mma_sync(c[mf][nf], a[mf], bfr, c[mf][nf]);
            }
        }
    }

    // ---- scaled scatter epilogue ----
    __syncthreads();
    float* buf = sm.ebuf[wid];
    int grow = m0 + wm * 32 + lane;
    bool ok = grow < cnt;
    int   tok = 0, ks = 0;
    float w = 0.f;
    if (ok) {
        tok = g_tok[e * T_TOK + grow];
        w   = g_wt [e * T_TOK + grow];
        ks  = g_kslot[e * T_TOK + grow];
    }
    size_t ybase = ((size_t)tok * 2 + ks) * DHID + n0 + wn * 64;

#pragma unroll
    for (int half = 0; half < 2; half++) {
        __syncwarp();
#pragma unroll
        for (int mf = 0; mf < 2; mf++)
#pragma unroll
            for (int nf = 0; nf < 2; nf++)
                wmma::store_matrix_sync(&buf[mf * 16 * 36 + nf * 16], c[mf][half * 2 + nf], 36, wmma::mem_row_major);
        __syncwarp();
        if (ok) {
#pragma unroll
            for (int j = 0; j < 32; j += 2) {
                float2 v;
                v.x = buf[lane * 36 + j]     * w;
                v.y = buf[lane * 36 + j + 1] * w;
                *(float2*)&g_y[ybase + half * 32 + j] = v;
            }
        }
    }
}

// ---------------- combine ---------------------------------------------------
__global__ void combine_kernel(float* __restrict__ out) {
    int i  = blockIdx.x * blockDim.x + threadIdx.x;
    int t  = i / (DHID / 4);
    int d4 = i % (DHID / 4);
    const float4 a = *(const float4*)&g_y[((size_t)t * 2 + 0) * DHID + d4 * 4];
    const float4 b = *(const float4*)&g_y[((size_t)t * 2 + 1) * DHID + d4 * 4];
    float4 o;
    o.x = a.x + b.x; o.y = a.y + b.y; o.z = a.z + b.z; o.w = a.w + b.w;
    *(float4*)&out[(size_t)t * DHID + d4 * 4] = o;
}

// ---------------- launch ----------------------------------------------------
extern "C" void kernel_launch(void* const* d_in, const int* in_sizes, int n_in,
                              void* d_out, int out_size) {
    const float* x  = (const float*)d_in[0];
    const float* rw = (const float*)d_in[1];
    const float* wg = (const float*)d_in[2];
    const float* wu = (const float*)d_in[3];
    const float* wd = (const float*)d_in[4];
    float* out = (float*)d_out;

    cudaStream_t side;
    cudaStreamCreateWithFlags(&side, cudaStreamNonBlocking);
    cudaEvent_t evFork, evJoin;
    cudaEventCreateWithFlags(&evFork, cudaEventDisableTiming);
    cudaEventCreateWithFlags(&evJoin, cudaEventDisableTiming);

    cudaEventRecord(evFork, 0);
    cudaStreamWaitEvent(side, evFork, 0);

    const int CONV_BLKS = (NEXP * DHID * FINT) / (256 * 8);   // 5632
    conv_kernel<<<dim3(CONV_BLKS, 3), 256, 0, side>>>(wg, wu, wd);
    cudaEventRecord(evJoin, side);

    zero_counts_kernel<<<1, 32>>>();
    router_kernel<<<T_TOK / 8, 256>>>(x, rw);
    gather_x_kernel<<<dim3(T_TOK, NEXP), 128>>>(x);

    cudaStreamWaitEvent(0, evJoin, 0);

    gu_wmma_kernel  <<<dim3(FINT / 64, T_TOK / 64, NEXP), 128>>>();
    down_wmma_kernel<<<dim3(DHID / 128, T_TOK / 64, NEXP), 128>>>();
    combine_kernel<<<(T_TOK * DHID / 4) / 256, 256>>>(out);
}

// round 17
// speedup vs baseline: 1.0286x; 1.0286x over previous
#include <cuda_runtime.h>
#include <cuda_fp16.h>
#include <mma.h>
#include <math.h>
#include <stdint.h>

using namespace nvcuda;

#define T_TOK 2048
#define DHID  1024
#define FINT  1408
#define NEXP  8

// ---------------- device scratch (static: no allocations allowed) ----------
__device__ int            g_count[NEXP];
__device__ int            g_tok[NEXP * T_TOK];
__device__ float          g_wt [NEXP * T_TOK];
__device__ unsigned char  g_kslot[NEXP * T_TOK];

__device__ __half         g_x16[(size_t)NEXP * T_TOK * DHID];
__device__ __half         g_wg16[(size_t)NEXP * DHID * FINT];
__device__ __half         g_wu16[(size_t)NEXP * DHID * FINT];
__device__ __half         g_wd16[(size_t)NEXP * FINT * DHID];
__device__ __half         g_h16[(size_t)NEXP * T_TOK * FINT];
__device__ float          g_y[(size_t)T_TOK * 2 * DHID];

// ---------------- routing (fused with activation gather) -------------------
__global__ void zero_counts_kernel() {
    if (threadIdx.x < NEXP) g_count[threadIdx.x] = 0;
}

// One warp per token: logits, softmax, top-2, renorm, bucket AND copy the
// token's fp16 row into both expert slots (x row is L1-hot from logit pass).
__global__ void router_gather_kernel(const float* __restrict__ x,
                                     const float* __restrict__ rw) {
    int warp = (blockIdx.x * blockDim.x + threadIdx.x) >> 5;
    int lane = threadIdx.x & 31;
    if (warp >= T_TOK) return;
    const float* xt = x + (size_t)warp * DHID;

    float logit[NEXP];
#pragma unroll
    for (int e = 0; e < NEXP; e++) {
        const float* w = rw + (size_t)e * DHID;
        float s = 0.f;
        for (int i = lane; i < DHID; i += 32) s += xt[i] * w[i];
#pragma unroll
        for (int o = 16; o > 0; o >>= 1) s += __shfl_xor_sync(0xffffffffu, s, o);
        logit[e] = s;
    }

    int i1 = 0, i2 = 0, pos1 = 0, pos2 = 0;
    if (lane == 0) {
        float m = logit[0];
#pragma unroll
        for (int e = 1; e < NEXP; e++) m = fmaxf(m, logit[e]);
        float p[NEXP];
#pragma unroll
        for (int e = 0; e < NEXP; e++) p[e] = expf(logit[e] - m);
        float v1 = p[0];
#pragma unroll
        for (int e = 1; e < NEXP; e++) if (p[e] > v1) { v1 = p[e]; i1 = e; }
        float v2 = -1.f; i2 = -1;
#pragma unroll
        for (int e = 0; e < NEXP; e++) {
            if (e == i1) continue;
            if (p[e] > v2) { v2 = p[e]; i2 = e; }
        }
        float inv = 1.f / (v1 + v2);
        pos1 = atomicAdd(&g_count[i1], 1);
        g_tok[i1 * T_TOK + pos1] = warp;  g_wt[i1 * T_TOK + pos1] = v1 * inv;  g_kslot[i1 * T_TOK + pos1] = 0;
        pos2 = atomicAdd(&g_count[i2], 1);
        g_tok[i2 * T_TOK + pos2] = warp;  g_wt[i2 * T_TOK + pos2] = v2 * inv;  g_kslot[i2 * T_TOK + pos2] = 1;
    }
    i1   = __shfl_sync(0xffffffffu, i1, 0);
    i2   = __shfl_sync(0xffffffffu, i2, 0);
    pos1 = __shfl_sync(0xffffffffu, pos1, 0);
    pos2 = __shfl_sync(0xffffffffu, pos2, 0);

    __half* dst1 = g_x16 + ((size_t)i1 * T_TOK + pos1) * DHID;
    __half* dst2 = g_x16 + ((size_t)i2 * T_TOK + pos2) * DHID;
#pragma unroll
    for (int j = lane * 8; j < DHID; j += 256) {
        float4 v0 = *(const float4*)(xt + j);
        float4 v1 = *(const float4*)(xt + j + 4);
        __half h[8];
        h[0] = __float2half_rn(v0.x); h[1] = __float2half_rn(v0.y);
        h[2] = __float2half_rn(v0.z); h[3] = __float2half_rn(v0.w);
        h[4] = __float2half_rn(v1.x); h[5] = __float2half_rn(v1.y);
        h[6] = __float2half_rn(v1.z); h[7] = __float2half_rn(v1.w);
        uint4 packed = *(uint4*)h;
        *(uint4*)(dst1 + j) = packed;
        *(uint4*)(dst2 + j) = packed;
    }
}

// pre-convert fp32 weights -> fp16 (dest chosen in device code)
__global__ void __launch_bounds__(256) conv_kernel(const float* __restrict__ wg,
                                                   const float* __restrict__ wu,
                                                   const float* __restrict__ wd) {
    int which = blockIdx.y;
    const float* src = (which == 0) ? wg : (which == 1) ? wu : wd;
    __half* dst = (which == 0) ? g_wg16 : (which == 1) ? g_wu16 : g_wd16;
    size_t i = ((size_t)blockIdx.x * 256 + threadIdx.x) * 8;
    float4 v0 = *(const float4*)(src + i);
    float4 v1 = *(const float4*)(src + i + 4);
    __half h[8];
    h[0] = __float2half_rn(v0.x); h[1] = __float2half_rn(v0.y);
    h[2] = __float2half_rn(v0.z); h[3] = __float2half_rn(v0.w);
    h[4] = __float2half_rn(v1.x); h[5] = __float2half_rn(v1.y);
    h[6] = __float2half_rn(v1.z); h[7] = __float2half_rn(v1.w);
    *(uint4*)(dst + i) = *(uint4*)h;
}

// ---------------- gate+up WMMA GEMM: reg prefetch + double-buffered smem ---
// Block tile: 128m x 64n, two B matrices, k-tile 32. 8 warps = 4m x 2n.
__global__ void __launch_bounds__(256) gu_wmma_kernel() {
    int e   = blockIdx.z;
    int cnt = g_count[e];
    int m0  = blockIdx.y * 128;
    if (m0 >= cnt) return;
    int n0  = blockIdx.x * 64;

    __shared__ union {
        struct {
            __half A[2][128][40];
            __half B[2][2][32][72];
        } ld;
        float ebuf[8][32 * 36];
    } sm;

    int tid = threadIdx.x, wid = tid >> 5, lane = tid & 31;
    int wm = wid & 3, wn = wid >> 2;

    const __half* W0 = g_wg16 + (size_t)e * DHID * FINT + n0;
    const __half* W1 = g_wu16 + (size_t)e * DHID * FINT + n0;
    size_t aBase = (size_t)e * T_TOK + m0;

    int ar = tid >> 2, ac = tid & 3;
    int bk = tid >> 3, bc = tid & 7;

    const __half* aP0 = g_x16 + (aBase + ar)      * DHID + ac * 8;
    const __half* aP1 = g_x16 + (aBase + ar + 64) * DHID + ac * 8;
    const __half* bP0 = W0 + (size_t)bk * FINT + bc * 8;
    const __half* bP1 = W1 + (size_t)bk * FINT + bc * 8;

    wmma::fragment<wmma::accumulator, 16, 16, 16, float> c[2][2][2];
#pragma unroll
    for (int mat = 0; mat < 2; mat++)
#pragma unroll
        for (int mf = 0; mf < 2; mf++)
#pragma unroll
            for (int nf = 0; nf < 2; nf++)
                wmma::fill_fragment(c[mat][mf][nf], 0.0f);

    uint4 ra0, ra1, rb0, rb1;
    ra0 = *(const uint4*)(aP0);
    ra1 = *(const uint4*)(aP1);
    rb0 = *(const uint4*)(bP0);
    rb1 = *(const uint4*)(bP1);

    const int NT = DHID / 32;   // 32
    for (int t = 0; t < NT; t++) {
        int b = t & 1;
        *(uint4*)&sm.ld.A[b][ar][ac * 8]      = ra0;
        *(uint4*)&sm.ld.A[b][ar + 64][ac * 8] = ra1;
        *(uint4*)&sm.ld.B[b][0][bk][bc * 8]   = rb0;
        *(uint4*)&sm.ld.B[b][1][bk][bc * 8]   = rb1;
        __syncthreads();
        if (t + 1 < NT) {
            int k1 = (t + 1) * 32;
            ra0 = *(const uint4*)(aP0 + k1);
            ra1 = *(const uint4*)(aP1 + k1);
            rb0 = *(const uint4*)(bP0 + (size_t)k1 * FINT);
            rb1 = *(const uint4*)(bP1 + (size_t)k1 * FINT);
        }

#pragma unroll
        for (int kk16 = 0; kk16 < 32; kk16 += 16) {
            wmma::fragment<wmma::matrix_a, 16, 16, 16, __half, wmma::row_major> a[2];
#pragma unroll
            for (int mf = 0; mf < 2; mf++)
                wmma::load_matrix_sync(a[mf], &sm.ld.A[b][wm * 32 + mf * 16][kk16], 40);
#pragma unroll
            for (int mat = 0; mat < 2; mat++) {
#pragma unroll
                for (int nf = 0; nf < 2; nf++) {
                    wmma::fragment<wmma::matrix_b, 16, 16, 16, __half, wmma::row_major> bfr;
                    wmma::load_matrix_sync(bfr, &sm.ld.B[b][mat][kk16][wn * 32 + nf * 16], 72);
#pragma unroll
                    for (int mf = 0; mf < 2; mf++)
                        wmma::mma_sync(c[mat][mf][nf], a[mf], bfr, c[mat][mf][nf]);
                }
            }
        }
    }

    // ---- fused SwiGLU epilogue ----
    __syncthreads();
    float* buf = sm.ebuf[wid];
    int grow = m0 + wm * 32 + lane;
    bool ok = grow < cnt;
    size_t hbase = ((size_t)e * T_TOK + grow) * FINT + n0 + wn * 32;

#pragma unroll
    for (int mf = 0; mf < 2; mf++)
#pragma unroll
        for (int nf = 0; nf < 2; nf++)
            wmma::store_matrix_sync(&buf[mf * 16 * 36 + nf * 16], c[0][mf][nf], 36, wmma::mem_row_major);
    __syncwarp();
    float gv[32];
#pragma unroll
    for (int j = 0; j < 32; j++) gv[j] = buf[lane * 36 + j];
    __syncwarp();
#pragma unroll
    for (int mf = 0; mf < 2; mf++)
#pragma unroll
        for (int nf = 0; nf < 2; nf++)
            wmma::store_matrix_sync(&buf[mf * 16 * 36 + nf * 16], c[1][mf][nf], 36, wmma::mem_row_major);
    __syncwarp();
    if (ok) {
#pragma unroll
        for (int j = 0; j < 32; j += 2) {
            float u0 = buf[lane * 36 + j];
            float u1 = buf[lane * 36 + j + 1];
            float g0 = gv[j], g1 = gv[j + 1];
            float h0 = g0 / (1.f + expf(-g0)) * u0;
            float h1 = g1 / (1.f + expf(-g1)) * u1;
            __half2 vh;
            vh.x = __float2half_rn(h0);
            vh.y = __float2half_rn(h1);
            *(__half2*)&g_h16[hbase + j] = vh;
        }
    }
}

// ---------------- down WMMA GEMM: reg prefetch + double-buffered smem ------
// Block tile 128m x 128n, k-tile 32; 8 warps = 4m x 2n; warp tile 32 x 64.
__global__ void __launch_bounds__(256) down_wmma_kernel() {
    int e   = blockIdx.z;
    int cnt = g_count[e];
    int m0  = blockIdx.y * 128;
    if (m0 >= cnt) return;
    int n0  = blockIdx.x * 128;

    __shared__ union {
        struct {
            __half A[2][128][40];
            __half B[2][32][136];
        } ld;
        float ebuf[8][32 * 36];
    } sm;

    int tid = threadIdx.x, wid = tid >> 5, lane = tid & 31;
    int wm = wid & 3, wn = wid >> 2;

    const __half* W = g_wd16 + (size_t)e * FINT * DHID + n0;
    size_t aBase = (size_t)e * T_TOK + m0;

    int ar = tid >> 2, ac = tid & 3;
    int bk = tid >> 4, bc = tid & 15;

    const __half* aP0 = g_h16 + (aBase + ar)      * FINT + ac * 8;
    const __half* aP1 = g_h16 + (aBase + ar + 64) * FINT + ac * 8;
    const __half* bP0 = W + (size_t)bk * DHID + bc * 8;
    const __half* bP1 = W + (size_t)(bk + 16) * DHID + bc * 8;

    wmma::fragment<wmma::accumulator, 16, 16, 16, float> c[2][4];
#pragma unroll
    for (int mf = 0; mf < 2; mf++)
#pragma unroll
        for (int nf = 0; nf < 4; nf++)
            wmma::fill_fragment(c[mf][nf], 0.0f);

    uint4 ra0, ra1, rb0, rb1;
    ra0 = *(const uint4*)(aP0);
    ra1 = *(const uint4*)(aP1);
    rb0 = *(const uint4*)(bP0);
    rb1 = *(const uint4*)(bP1);

    const int NT = FINT / 32;   // 44
    for (int t = 0; t < NT; t++) {
        int b = t & 1;
        *(uint4*)&sm.ld.A[b][ar][ac * 8]      = ra0;
        *(uint4*)&sm.ld.A[b][ar + 64][ac * 8] = ra1;
        *(uint4*)&sm.ld.B[b][bk][bc * 8]      = rb0;
        *(uint4*)&sm.ld.B[b][bk + 16][bc * 8] = rb1;
        __syncthreads();
        if (t + 1 < NT) {
            int k1 = (t + 1) * 32;
            ra0 = *(const uint4*)(aP0 + k1);
            ra1 = *(const uint4*)(aP1 + k1);
            rb0 = *(const uint4*)(bP0 + (size_t)k1 * DHID);
            rb1 = *(const uint4*)(bP1 + (size_t)k1 * DHID);
        }

#pragma unroll
        for (int kk16 = 0; kk16 < 32; kk16 += 16) {
            wmma::fragment<wmma::matrix_a, 16, 16, 16, __half, wmma::row_major> a[2];
#pragma unroll
            for (int mf = 0; mf < 2; mf++)
                wmma::load_matrix_sync(a[mf], &sm.ld.A[b][wm * 32 + mf * 16][kk16], 40);
#pragma unroll
            for (int nf = 0; nf < 4; nf++) {
                wmma::fragment<wmma::matrix_b, 16, 16, 16, __half, wmma::row_major> bfr;
                wmma::load_matrix_sync(bfr, &sm.ld.B[b][kk16][wn * 64 + nf * 16], 136);
#pragma unroll
                for (int mf = 0; mf < 2; mf++)
                    wmma::mma_sync(c[mf][nf], a[mf], bfr, c[mf][nf]);
            }
        }
    }

    // ---- scaled scatter epilogue ----
    __syncthreads();
    float* buf = sm.ebuf[wid];
    int grow = m0 + wm * 32 + lane;
    bool ok = grow < cnt;
    int   tok = 0, ks = 0;
    float w = 0.f;
    if (ok) {
        tok = g_tok[e * T_TOK + grow];
        w   = g_wt [e * T_TOK + grow];
        ks  = g_kslot[e * T_TOK + grow];
    }
    size_t ybase = ((size_t)tok * 2 + ks) * DHID + n0 + wn * 64;

#pragma unroll
    for (int half = 0; half < 2; half++) {
        __syncwarp();
#pragma unroll
        for (int mf = 0; mf < 2; mf++)
#pragma unroll
            for (int nf = 0; nf < 2; nf++)
                wmma::store_matrix_sync(&buf[mf * 16 * 36 + nf * 16], c[mf][half * 2 + nf], 36, wmma::mem_row_major);
        __syncwarp();
        if (ok) {
#pragma unroll
            for (int j = 0; j < 32; j += 2) {
                float2 v;
                v.x = buf[lane * 36 + j]     * w;
                v.y = buf[lane * 36 + j + 1] * w;
                *(float2*)&g_y[ybase + half * 32 + j] = v;
            }
        }
    }
}

// ---------------- combine ---------------------------------------------------
__global__ void combine_kernel(float* __restrict__ out) {
    int i  = blockIdx.x * blockDim.x + threadIdx.x;
    int t  = i / (DHID / 4);
    int d4 = i % (DHID / 4);
    const float4 a = *(const float4*)&g_y[((size_t)t * 2 + 0) * DHID + d4 * 4];
    const float4 b = *(const float4*)&g_y[((size_t)t * 2 + 1) * DHID + d4 * 4];
    float4 o;
    o.x = a.x + b.x; o.y = a.y + b.y; o.z = a.z + b.z; o.w = a.w + b.w;
    *(float4*)&out[(size_t)t * DHID + d4 * 4] = o;
}

// ---------------- launch ----------------------------------------------------
extern "C" void kernel_launch(void* const* d_in, const int* in_sizes, int n_in,
                              void* d_out, int out_size) {
    const float* x  = (const float*)d_in[0];
    const float* rw = (const float*)d_in[1];
    const float* wg = (const float*)d_in[2];
    const float* wu = (const float*)d_in[3];
    const float* wd = (const float*)d_in[4];
    float* out = (float*)d_out;

    zero_counts_kernel<<<1, 32>>>();
    router_gather_kernel<<<T_TOK / 8, 256>>>(x, rw);

    const int CONV_BLKS = (NEXP * DHID * FINT) / (256 * 8);   // 5632
    conv_kernel<<<dim3(CONV_BLKS, 3), 256>>>(wg, wu, wd);

    gu_wmma_kernel  <<<dim3(FINT / 64, T_TOK / 128, NEXP), 256>>>();
    down_wmma_kernel<<<dim3(DHID / 128, T_TOK / 128, NEXP), 256>>>();

    combine_kernel<<<(T_TOK * DHID / 4) / 256, 256>>>(out);
}